// round 8
// baseline (speedup 1.0000x reference)
#include <cuda_runtime.h>
#include <cuda_bf16.h>
#include <cstdint>

// DeChunkLayer collapses to a gather:
//   cum[b,s]   = inclusive cumsum of boundary_mask along s
//   out[b,s,:] = cum>0 ? compressed_states[b, cum-1, :] : 0
// Bulk-async version: per block, 8x 4KB cp.async.bulk loads (gmem->smem)
// + one 32KB cp.async.bulk store (smem->gmem, rows are contiguous).
// Data never touches registers; LSU issue pressure ~0.

#define B_ 8
#define S_ 4096
#define D_ 1024
#define ROWS_PER_BLK 8
#define ROW_BYTES 4096

__device__ __forceinline__ uint32_t smem_u32(const void* p) {
    uint32_t a;
    asm("{ .reg .u64 t; cvta.to.shared.u64 t, %1; cvt.u32.u64 %0, t; }"
        : "=r"(a) : "l"(p));
    return a;
}

__global__ void __launch_bounds__(128)
fused_kernel(const float* __restrict__ cs,
             const int* __restrict__ mask,
             float* __restrict__ out)
{
    __shared__ alignas(128) float sbuf[ROWS_PER_BLK * D_];   // 32 KB
    __shared__ int rows[ROWS_PER_BLK];
    __shared__ int s_nvalid;
    __shared__ alignas(8) unsigned long long mbar;

    const int base = blockIdx.x * ROWS_PER_BLK;   // global (b*S+s) of first row
    const int b    = base >> 12;                  // / S_
    const int s0   = base & (S_ - 1);
    const int t    = threadIdx.x;                 // 0..127
    const int lane = t & 31;
    const int warp = t >> 5;

    const int* mrow = mask + (size_t)b * S_;

    // ---- 1) count boundaries in [0, s0) --------------------------------
    int cnt = 0;
    const int4* m4 = reinterpret_cast<const int4*>(mrow);
    for (int i = t; i < (s0 >> 2); i += 128) {
        int4 v = __ldg(&m4[i]);
        cnt += (v.x != 0) + (v.y != 0) + (v.z != 0) + (v.w != 0);
    }
    #pragma unroll
    for (int o = 16; o; o >>= 1)
        cnt += __shfl_xor_sync(0xffffffffu, cnt, o);

    __shared__ int ws[4];
    if (lane == 0) ws[warp] = cnt;
    if (t == 0) {
        asm volatile("mbarrier.init.shared.b64 [%0], 1;"
                     :: "r"(smem_u32(&mbar)) : "memory");
    }
    __syncthreads();

    // ---- 2) warp 0: total + inclusive scan of this block's 8 mask bits -
    if (warp == 0) {
        int v = (lane < 4) ? ws[lane] : 0;
        #pragma unroll
        for (int o = 2; o; o >>= 1)
            v += __shfl_xor_sync(0xffffffffu, v, o);
        int total = __shfl_sync(0xffffffffu, v, 0);

        int m = (lane < ROWS_PER_BLK) ? (mrow[s0 + lane] != 0) : 0;
        int incl = m;
        #pragma unroll
        for (int o = 1; o < ROWS_PER_BLK; o <<= 1) {
            int n = __shfl_up_sync(0xffffffffu, incl, o);
            if (lane >= o) incl += n;
        }
        int r = total + incl - 1;                 // -1 => zeros
        if (lane < ROWS_PER_BLK) rows[lane] = r;
        // n_valid = count of lanes (<8) with r >= 0
        unsigned bal = __ballot_sync(0xffffffffu, lane < ROWS_PER_BLK && r >= 0);
        if (lane == 0) s_nvalid = __popc(bal);
    }
    __syncthreads();

    const uint32_t smem_base = smem_u32(sbuf);

    // ---- 3) issue bulk loads (thread 0) --------------------------------
    if (t == 0) {
        asm volatile("mbarrier.arrive.expect_tx.shared.b64 _, [%0], %1;"
                     :: "r"(smem_u32(&mbar)), "r"((uint32_t)(s_nvalid * ROW_BYTES))
                     : "memory");
        #pragma unroll
        for (int r = 0; r < ROWS_PER_BLK; r++) {
            int row = rows[r];
            if (row >= 0) {
                const float* src = cs + ((size_t)b * S_ + row) * D_;
                asm volatile(
                    "cp.async.bulk.shared::cta.global.mbarrier::complete_tx::bytes "
                    "[%0], [%1], %2, [%3];"
                    :: "r"(smem_base + r * ROW_BYTES), "l"(src),
                       "r"((uint32_t)ROW_BYTES), "r"(smem_u32(&mbar))
                    : "memory");
            }
        }
    }

    // ---- 4) zero-fill invalid rows (rare) ------------------------------
    #pragma unroll
    for (int r = 0; r < ROWS_PER_BLK; r++) {
        if (rows[r] < 0) {
            float4* dst = reinterpret_cast<float4*>(sbuf + r * D_);
            for (int i = t; i < D_ / 4; i += 128)
                dst[i] = make_float4(0.f, 0.f, 0.f, 0.f);
        }
    }
    __syncthreads();   // zero-fill visible before store issue

    // ---- 5) wait for loads, then one 32KB bulk store -------------------
    if (t == 0) {
        uint32_t mb = smem_u32(&mbar);
        uint32_t done;
        asm volatile(
            "{\n\t.reg .pred p;\n\t"
            "mbarrier.try_wait.parity.shared.b64 p, [%1], 0;\n\t"
            "selp.b32 %0, 1, 0, p;\n\t}"
            : "=r"(done) : "r"(mb) : "memory");
        while (!done) {
            asm volatile(
                "{\n\t.reg .pred p;\n\t"
                "mbarrier.try_wait.parity.shared.b64 p, [%1], 0;\n\t"
                "selp.b32 %0, 1, 0, p;\n\t}"
                : "=r"(done) : "r"(mb) : "memory");
        }
        asm volatile("fence.proxy.async.shared::cta;" ::: "memory");
        float* dst = out + (size_t)base * D_;
        asm volatile(
            "cp.async.bulk.global.shared::cta.bulk_group [%0], [%1], %2;"
            :: "l"(dst), "r"(smem_base),
               "r"((uint32_t)(ROWS_PER_BLK * ROW_BYTES))
            : "memory");
        asm volatile("cp.async.bulk.commit_group;" ::: "memory");
        asm volatile("cp.async.bulk.wait_group 0;" ::: "memory");
    }
    __syncthreads();   // keep smem alive until the bulk store has read it
}

// ---------------------------------------------------------------------------
extern "C" void kernel_launch(void* const* d_in, const int* in_sizes, int n_in,
                              void* d_out, int out_size)
{
    const float* cs = nullptr;
    const int*   mask = nullptr;
    for (int i = 0; i < n_in; i++) {
        if (in_sizes[i] == B_ * S_ * D_)      cs   = (const float*)d_in[i];
        else if (in_sizes[i] == B_ * S_)      mask = (const int*)d_in[i];
    }
    float* out = (float*)d_out;

    fused_kernel<<<(B_ * S_) / ROWS_PER_BLK, 128>>>(cs, mask, out);
}